// round 14
// baseline (speedup 1.0000x reference)
#include <cuda_runtime.h>
#include <cstdint>

#define B_SZ 512
#define IN_F 512
#define OUT_F 100
#define KD 5
#define KP 6                // padded kernel dim (row stride per o)
#define OCP 600             // OUT_F * KP, padded row stride
#define OC 500              // OUT_F * KD (unpadded, T layout)
#define LOG2E 1.4426950408889634f
#define NT 32               // number of batch tiles
#define TS 16               // tile size (NT*TS = B_SZ)
#define NP 528              // NT*(NT+1)/2 unordered tile pairs

// Scratch for M = (x @ T) * log2(e), padded layout [b][o*6+k], 1.2MB
__device__ float g_M[B_SZ * OCP];

__device__ __forceinline__ float ex2(float x) {
    float r;
    asm("ex2.approx.f32 %0, %1;" : "=f"(r) : "f"(x));
    return r;
}

// ---------------------------------------------------------------------------
// Kernel 1: M[b][o*6+k] = sum_i x[b][i] * T[i][o*5+k], scaled by log2e.
// T-reuse doubled: 16 b-rows per block with FULL grid coverage.
// Grid (32 b-tiles, 8 oc-slices) = 256 blocks; block 512 = 64 oc-lanes x
// 8 K-slices (kh). Each thread: 16 b-row accumulators, scalar T load
// (4 FFMA per T byte -> 32MB total L2 traffic, 2.6us floor). kh-slices
// tree-reduced via smem. Padded epilogue. Also zeroes `out` (oc-slice 0).
// ---------------------------------------------------------------------------
__global__ void __launch_bounds__(512, 2) gemm_kernel(const float* __restrict__ x,
                                                      const float* __restrict__ T,
                                                      float* __restrict__ out) {
    __shared__ __align__(16) float xs[IN_F * 16];         // [i][bb], 32KB
    __shared__ __align__(16) float red[4 * 16 * 64];      // 4 slices, 16KB

    const int t = threadIdx.x;
    const int lane = t & 63;               // oc lane (scalar)
    const int kh = t >> 6;                 // 0..7
    const int b0 = blockIdx.x * 16;        // 0..496
    const int oc = blockIdx.y * 64 + lane; // 0..511
    const bool ocv = (oc < OC);

    if (blockIdx.y == 0) {
        for (int idx = blockIdx.x * 512 + t; idx < B_SZ * OUT_F; idx += 32 * 512)
            out[idx] = 0.0f;
    }

    // cooperative transpose load: x[b0+bb][i] -> xs[i*16+bb]
    for (int idx = t; idx < IN_F * 16; idx += 512) {
        int bb = idx >> 9;                 // 0..15
        int i = idx & (IN_F - 1);          // 0..511
        xs[i * 16 + bb] = x[(b0 + bb) * IN_F + i];
    }
    __syncthreads();

    float acc[16];
#pragma unroll
    for (int bb = 0; bb < 16; bb++) acc[bb] = 0.f;

    if (ocv) {
        const float* tp = T + (size_t)(kh * 64) * OC + oc;
        const float* xp = xs + kh * 64 * 16;
#pragma unroll 4
        for (int i = 0; i < 64; i++) {
            float tv = tp[i * OC];
            const float4* row = reinterpret_cast<const float4*>(xp + i * 16);
            float4 xa = row[0];
            float4 xb = row[1];
            acc[0] += xa.x * tv; acc[1] += xa.y * tv;
            acc[2] += xa.z * tv; acc[3] += xa.w * tv;
            acc[4] += xb.x * tv; acc[5] += xb.y * tv;
            acc[6] += xb.z * tv; acc[7] += xb.w * tv;
            float4 xc = row[2];
            float4 xd = row[3];
            acc[8]  += xc.x * tv; acc[9]  += xc.y * tv;
            acc[10] += xc.z * tv; acc[11] += xc.w * tv;
            acc[12] += xd.x * tv; acc[13] += xd.y * tv;
            acc[14] += xd.z * tv; acc[15] += xd.w * tv;
        }
    }

    // tree reduction of 8 kh-slices (3 steps) through 4-slice buffer
    // red layout: [slice][bb][lane], slice stride 1024
    if (kh >= 4) {
        float* rp = red + (kh - 4) * 1024 + lane;
#pragma unroll
        for (int bb = 0; bb < 16; bb++) rp[bb * 64] = acc[bb];
    }
    __syncthreads();
    if (kh < 4) {
        const float* rp = red + kh * 1024 + lane;
#pragma unroll
        for (int bb = 0; bb < 16; bb++) acc[bb] += rp[bb * 64];
    }
    __syncthreads();
    if (kh == 2 || kh == 3) {
        float* rp = red + (kh - 2) * 1024 + lane;
#pragma unroll
        for (int bb = 0; bb < 16; bb++) rp[bb * 64] = acc[bb];
    }
    __syncthreads();
    if (kh < 2) {
        const float* rp = red + kh * 1024 + lane;
#pragma unroll
        for (int bb = 0; bb < 16; bb++) acc[bb] += rp[bb * 64];
    }
    __syncthreads();
    if (kh == 1) {
        float* rp = red + lane;
#pragma unroll
        for (int bb = 0; bb < 16; bb++) rp[bb * 64] = acc[bb];
    }
    __syncthreads();
    if (kh == 0 && ocv) {
        const int o0 = oc / 5;
        const int k0 = oc - o0 * 5;
        const size_t off = (size_t)o0 * KP + k0;
#pragma unroll
        for (int bb = 0; bb < 16; bb++) {
            float s = (acc[bb] + red[bb * 64 + lane]) * LOG2E;
            g_M[(size_t)(b0 + bb) * OCP + off] = s;
        }
    }
}

// ---------------------------------------------------------------------------
// Kernel 2 (exact R12 best: symmetric, branchless hot loop): one block per
// unordered tile pair, 528 blocks, 416 threads; t<400: o = t>>2, jl = t&3,
// JR=4. Straight-line 16-deep ii loop (3 LDS + 4 evals + 1 reg store);
// butterfly reductions and all atomics in the epilogue.
// ---------------------------------------------------------------------------
__global__ void __launch_bounds__(416, 2) md_kernel(float* __restrict__ out) {
    __shared__ __align__(16) float ms[TS * OCP];  // 38.4KB

    int rem = blockIdx.x;
    int ta = 0;
    while (rem >= NT - ta) { rem -= NT - ta; ta++; }
    const int tb = ta + rem;
    const bool diag = (ta == tb);

    const int t = threadIdx.x;
    const bool act = (t < 400);
    const int o = act ? (t >> 2) : 99;
    const int jl = t & 3;

    // stage tile_a: 16 rows x 600 floats = 2400 float4
    {
        const float4* src = reinterpret_cast<const float4*>(g_M + (size_t)ta * TS * OCP);
        float4* dst = reinterpret_cast<float4*>(ms);
        for (int i = t; i < 2400; i += 416) dst[i] = src[i];
    }

#define DECL_A(R)                                                              \
    float a##R##0, a##R##1, a##R##2, a##R##3, a##R##4;                         \
    {                                                                          \
        const int j = tb * TS + jl + 4 * (R);                                  \
        const float* m = g_M + (size_t)j * OCP + o * KP;                       \
        float2 v01 = *reinterpret_cast<const float2*>(m);                      \
        float2 v23 = *reinterpret_cast<const float2*>(m + 2);                  \
        a##R##0 = v01.x; a##R##1 = v01.y;                                      \
        a##R##2 = v23.x; a##R##3 = v23.y;                                      \
        a##R##4 = m[4];                                                        \
    }
    DECL_A(0)
    DECL_A(1)
    DECL_A(2)
    DECL_A(3)
#undef DECL_A

    float accJ0 = 0.f, accJ1 = 0.f, accJ2 = 0.f, accJ3 = 0.f;
    float accI[TS];
#pragma unroll
    for (int ii = 0; ii < TS; ii++) accI[ii] = 0.f;

    __syncthreads();

    const float* mp = ms + o * KP;

#define EVAL(R, ACC)                                                           \
    {                                                                          \
        float pa = -fabsf(d01.x - a##R##0) - fabsf(d01.y - a##R##1);           \
        float qa = -fabsf(d23.x - a##R##2) - fabsf(d23.y - a##R##3);           \
        float n = (pa + qa) - fabsf(d4 - a##R##4);                             \
        float e = ex2(n);                                                      \
        ACC += e;                                                              \
        loc += e;                                                              \
    }

#pragma unroll
    for (int ii = 0; ii < TS; ii++) {
        const float* m = mp + ii * OCP;
        float2 d01 = *reinterpret_cast<const float2*>(m);
        float2 d23 = *reinterpret_cast<const float2*>(m + 2);
        float d4 = m[4];
        float loc = 0.f;
        EVAL(0, accJ0)
        EVAL(1, accJ1)
        EVAL(2, accJ2)
        EVAL(3, accJ3)
        accI[ii] = loc;
    }
#undef EVAL

#pragma unroll
    for (int ii = 0; ii < TS; ii++) {
        float v = accI[ii];
        v += __shfl_xor_sync(0xffffffffu, v, 1);
        v += __shfl_xor_sync(0xffffffffu, v, 2);
        accI[ii] = v;
    }

    if (act) {
        if (!diag) {
#pragma unroll
            for (int q = 0; q < 4; q++) {
                float v = (jl == 0) ? accI[q]
                        : (jl == 1) ? accI[4 + q]
                        : (jl == 2) ? accI[8 + q]
                                    : accI[12 + q];
                const int ii = jl * 4 + q;
                atomicAdd(&out[(ta * TS + ii) * OUT_F + o], v);
            }
        }
        const float sub = diag ? 1.0f : 0.0f;
        atomicAdd(&out[(tb * TS + jl + 0)  * OUT_F + o], accJ0 - sub);
        atomicAdd(&out[(tb * TS + jl + 4)  * OUT_F + o], accJ1 - sub);
        atomicAdd(&out[(tb * TS + jl + 8)  * OUT_F + o], accJ2 - sub);
        atomicAdd(&out[(tb * TS + jl + 12) * OUT_F + o], accJ3 - sub);
    }
}

extern "C" void kernel_launch(void* const* d_in, const int* in_sizes, int n_in,
                              void* d_out, int out_size) {
    const float* x = (const float*)d_in[0];   // [512, 512]
    const float* T = (const float*)d_in[1];   // [512, 100, 5] -> [512, 500]
    float* out = (float*)d_out;               // [512, 100]

    gemm_kernel<<<dim3(32, 8), 512>>>(x, T, out);
    md_kernel<<<NP, 416>>>(out);
}

// round 15
// speedup vs baseline: 1.2087x; 1.2087x over previous
#include <cuda_runtime.h>
#include <cstdint>

#define B_SZ 512
#define IN_F 512
#define OUT_F 100
#define KD 5
#define OC 500              // OUT_F * KD
#define LOG2E 1.4426950408889634f
#define NT 32               // number of batch tiles
#define TS 16               // tile size (NT*TS = B_SZ)
#define NP 528              // NT*(NT+1)/2 unordered tile pairs

// Scratch for M = (x @ T) * log2(e), laid out [b][o*5+k], 512x500 floats = 1MB
__device__ float g_M[B_SZ * OC];

__device__ __forceinline__ float ex2(float x) {
    float r;
    asm("ex2.approx.f32 %0, %1;" : "=f"(r) : "f"(x));
    return r;
}

// ---------------------------------------------------------------------------
// Kernel 1 (EXACT R6 gemm — best measured in total): M[b][oc] =
// sum_i x[b][i] * T[i][oc], scaled by log2e. Block: 512 threads = 64
// oc-pair-lanes x 8 K-slices (kh); 8 b-rows x 2 oc per thread (float2 T
// loads) over a 64-long K-slice; slices reduced through 28KB smem (linear).
// Grid (64, 4). Also zeroes `out` (blockIdx.y == 0 slice).
// ---------------------------------------------------------------------------
__global__ void __launch_bounds__(512) gemm_kernel(const float* __restrict__ x,
                                                   const float* __restrict__ T,
                                                   float* __restrict__ out) {
    __shared__ __align__(16) float xs[IN_F * 8];          // [i][bb], 16KB
    __shared__ __align__(16) float red[7 * 8 * 128];      // kh=1..7 partials, 28KB

    const int t = threadIdx.x;
    const int lane = t & 63;               // oc-pair lane
    const int kh = t >> 6;                 // 0..7
    const int b0 = blockIdx.x * 8;
    const int oc0 = blockIdx.y * 128;
    const int oc = oc0 + lane * 2;
    const bool ocv = (oc < OC);

    if (blockIdx.y == 0) {
        for (int idx = blockIdx.x * 512 + t; idx < B_SZ * OUT_F; idx += 64 * 512)
            out[idx] = 0.0f;
    }

    // cooperative transpose load: x[b0+bb][i] -> xs[i*8+bb]
    for (int idx = t; idx < IN_F * 8; idx += 512) {
        int bb = idx >> 9;
        int i = idx & (IN_F - 1);
        xs[i * 8 + bb] = x[(b0 + bb) * IN_F + i];
    }
    __syncthreads();

    float accx[8] = {0.f, 0.f, 0.f, 0.f, 0.f, 0.f, 0.f, 0.f};
    float accy[8] = {0.f, 0.f, 0.f, 0.f, 0.f, 0.f, 0.f, 0.f};

    if (ocv) {
        const float* tp = T + (size_t)(kh * 64) * OC + oc;
        const float* xp = xs + kh * 64 * 8;
#pragma unroll 8
        for (int i = 0; i < 64; i++) {
            float2 tv = *reinterpret_cast<const float2*>(tp + i * OC);
            float4 xa = *reinterpret_cast<const float4*>(xp + i * 8);
            float4 xb = *reinterpret_cast<const float4*>(xp + i * 8 + 4);
            accx[0] += xa.x * tv.x; accy[0] += xa.x * tv.y;
            accx[1] += xa.y * tv.x; accy[1] += xa.y * tv.y;
            accx[2] += xa.z * tv.x; accy[2] += xa.z * tv.y;
            accx[3] += xa.w * tv.x; accy[3] += xa.w * tv.y;
            accx[4] += xb.x * tv.x; accy[4] += xb.x * tv.y;
            accx[5] += xb.y * tv.x; accy[5] += xb.y * tv.y;
            accx[6] += xb.z * tv.x; accy[6] += xb.z * tv.y;
            accx[7] += xb.w * tv.x; accy[7] += xb.w * tv.y;
        }
    }

    if (kh > 0) {
        float* rp = red + (kh - 1) * 1024 + lane * 2;
#pragma unroll
        for (int bb = 0; bb < 8; bb++) {
            rp[bb * 128 + 0] = accx[bb];
            rp[bb * 128 + 1] = accy[bb];
        }
    }
    __syncthreads();
    if (kh == 0 && ocv) {
#pragma unroll
        for (int bb = 0; bb < 8; bb++) {
            float sx = accx[bb], sy = accy[bb];
#pragma unroll
            for (int s = 0; s < 7; s++) {
                sx += red[s * 1024 + bb * 128 + lane * 2 + 0];
                sy += red[s * 1024 + bb * 128 + lane * 2 + 1];
            }
            float2 o2;
            o2.x = sx * LOG2E;
            o2.y = sy * LOG2E;
            *reinterpret_cast<float2*>(&g_M[(size_t)(b0 + bb) * OC + oc]) = o2;
        }
    }
}

// ---------------------------------------------------------------------------
// Kernel 2 (symmetric, branchless hot loop on unpadded stride-5 layout):
// one block per unordered tile pair (ta <= tb), 528 blocks, 416 threads;
// t<400: o = t>>2, jl = t&3, JR=4 named-scalar j-rows. The 16-deep ii loop
// is straight-line (5 scalar LDS + 4 evals + 1 reg store); butterfly
// reductions (xor 1,2) and all atomics hoisted to the epilogue.
// Stride-5 smem rows are conflict-free across the 8 o's of a warp.
// ---------------------------------------------------------------------------
__global__ void __launch_bounds__(416, 2) md_kernel(float* __restrict__ out) {
    __shared__ __align__(16) float ms[TS * OC];  // 32KB

    int rem = blockIdx.x;
    int ta = 0;
    while (rem >= NT - ta) { rem -= NT - ta; ta++; }
    const int tb = ta + rem;
    const bool diag = (ta == tb);

    const int t = threadIdx.x;
    const bool act = (t < 400);
    const int o = act ? (t >> 2) : 99;   // clamp for safe reads
    const int jl = t & 3;

    // stage tile_a: 16 rows x 500 floats = 2000 float4
    {
        const float4* src = reinterpret_cast<const float4*>(g_M + (size_t)ta * TS * OC);
        float4* dst = reinterpret_cast<float4*>(ms);
        for (int i = t; i < 2000; i += 416) dst[i] = src[i];
    }

    // load 4 j-side rows into NAMED scalars
#define DECL_A(R)                                                              \
    float a##R##0, a##R##1, a##R##2, a##R##3, a##R##4;                         \
    {                                                                          \
        const int j = tb * TS + jl + 4 * (R);                                  \
        const float* m = g_M + (size_t)j * OC + o * KD;                        \
        a##R##0 = m[0]; a##R##1 = m[1]; a##R##2 = m[2];                        \
        a##R##3 = m[3]; a##R##4 = m[4];                                        \
    }
    DECL_A(0)
    DECL_A(1)
    DECL_A(2)
    DECL_A(3)
#undef DECL_A

    float accJ0 = 0.f, accJ1 = 0.f, accJ2 = 0.f, accJ3 = 0.f;
    float accI[TS];   // compile-time indexed only -> registers
#pragma unroll
    for (int ii = 0; ii < TS; ii++) accI[ii] = 0.f;

    __syncthreads();

    const float* mp = ms + o * KD;

#define EVAL(R, ACC)                                                           \
    {                                                                          \
        float pa = -fabsf(d0 - a##R##0) - fabsf(d1 - a##R##1);                 \
        float qa = -fabsf(d2 - a##R##2) - fabsf(d3 - a##R##3);                 \
        float n = (pa + qa) - fabsf(d4 - a##R##4);                             \
        float e = ex2(n);                                                      \
        ACC += e;                                                              \
        loc += e;                                                              \
    }

#pragma unroll
    for (int ii = 0; ii < TS; ii++) {
        const float* m = mp + ii * OC;
        float d0 = m[0], d1 = m[1], d2 = m[2], d3 = m[3], d4 = m[4];
        float loc = 0.f;
        EVAL(0, accJ0)
        EVAL(1, accJ1)
        EVAL(2, accJ2)
        EVAL(3, accJ3)
        accI[ii] = loc;
    }
#undef EVAL

    // Epilogue: butterfly-reduce each accI[ii] across the 4 jl-lanes.
#pragma unroll
    for (int ii = 0; ii < TS; ii++) {
        float v = accI[ii];
        v += __shfl_xor_sync(0xffffffffu, v, 1);
        v += __shfl_xor_sync(0xffffffffu, v, 2);
        accI[ii] = v;
    }

    if (act) {
        if (!diag) {
            // lane jl writes rows ii = jl*4 + q; compile-time selection only
#pragma unroll
            for (int q = 0; q < 4; q++) {
                float v = (jl == 0) ? accI[q]
                        : (jl == 1) ? accI[4 + q]
                        : (jl == 2) ? accI[8 + q]
                                    : accI[12 + q];
                const int ii = jl * 4 + q;
                atomicAdd(&out[(ta * TS + ii) * OUT_F + o], v);
            }
        }
        const float sub = diag ? 1.0f : 0.0f;
        atomicAdd(&out[(tb * TS + jl + 0)  * OUT_F + o], accJ0 - sub);
        atomicAdd(&out[(tb * TS + jl + 4)  * OUT_F + o], accJ1 - sub);
        atomicAdd(&out[(tb * TS + jl + 8)  * OUT_F + o], accJ2 - sub);
        atomicAdd(&out[(tb * TS + jl + 12) * OUT_F + o], accJ3 - sub);
    }
}

extern "C" void kernel_launch(void* const* d_in, const int* in_sizes, int n_in,
                              void* d_out, int out_size) {
    const float* x = (const float*)d_in[0];   // [512, 512]
    const float* T = (const float*)d_in[1];   // [512, 100, 5] -> [512, 500]
    float* out = (float*)d_out;               // [512, 100]

    gemm_kernel<<<dim3(64, 4), 512>>>(x, T, out);
    md_kernel<<<NP, 416>>>(out);
}